// round 2
// baseline (speedup 1.0000x reference)
#include <cuda_runtime.h>
#include <cstdint>

// Problem constants
#define B_  8
#define N_  1024
#define C_  256
#define H_  8
#define HD_ 64
#define KS_ 512
#define BH_ (B_ * H_)            // 64
#define HEAD_ELEMS_ 524288       // B*N*HD per head
#define SCALE_ 0.0625f           // 1/sqrt(256)

// Scratch (device globals: allocation-free rule)
__device__ float g_q[BH_ * N_ * HD_];        // [b,h,n,d] 16 MB
__device__ float g_k[BH_ * N_ * HD_];        // 16 MB
__device__ float g_part[1024 * 2];           // per-block partial (sum, sumsq)
__device__ float g_stats[16 * 2];            // [t*8+h]: mean, rstd
__device__ float g_scores[(size_t)BH_ * N_ * N_]; // S^T[b,h,m,n] 256 MB

// ---------------------------------------------------------------------------
// Kernel 1: q = x @ qw^T, k = x @ kw^T   (M=8192, Ncols=512, K=256)
// Writes directly into [b,h,n,d] layout. 128x128 tile, 8x8 per thread.
// ---------------------------------------------------------------------------
__global__ void __launch_bounds__(256) gemm_qk_kernel(const float* __restrict__ x,
                                                      const float* __restrict__ qw,
                                                      const float* __restrict__ kw) {
    __shared__ float As[16][132];
    __shared__ float Bs[16][132];
    const int tid = threadIdx.x;
    const float* wptr = blockIdx.z ? kw : qw;
    float* outp = blockIdx.z ? g_k : g_q;
    const int m0 = blockIdx.y * 128;
    const int n0 = blockIdx.x * 128;
    const int tx = tid & 15, ty = tid >> 4;

    float acc[8][8];
#pragma unroll
    for (int i = 0; i < 8; i++)
#pragma unroll
        for (int j = 0; j < 8; j++) acc[i][j] = 0.f;

    for (int kt = 0; kt < C_; kt += 16) {
#pragma unroll
        for (int i = 0; i < 2; i++) {
            int idx = tid + i * 256;       // 0..511 float4 slots
            int r = idx >> 2;              // row in tile 0..127
            int kq = idx & 3;              // which float4 of the 16-k chunk
            float4 va = *(const float4*)(x + (size_t)(m0 + r) * C_ + kt + kq * 4);
            As[kq * 4 + 0][r] = va.x; As[kq * 4 + 1][r] = va.y;
            As[kq * 4 + 2][r] = va.z; As[kq * 4 + 3][r] = va.w;
            float4 vb = *(const float4*)(wptr + (size_t)(n0 + r) * C_ + kt + kq * 4);
            Bs[kq * 4 + 0][r] = vb.x; Bs[kq * 4 + 1][r] = vb.y;
            Bs[kq * 4 + 2][r] = vb.z; Bs[kq * 4 + 3][r] = vb.w;
        }
        __syncthreads();
#pragma unroll
        for (int kk = 0; kk < 16; kk++) {
            float a[8], bv[8];
            *(float4*)(a)     = *(const float4*)&As[kk][ty * 8];
            *(float4*)(a + 4) = *(const float4*)&As[kk][ty * 8 + 4];
            *(float4*)(bv)     = *(const float4*)&Bs[kk][tx * 8];
            *(float4*)(bv + 4) = *(const float4*)&Bs[kk][tx * 8 + 4];
#pragma unroll
            for (int i = 0; i < 8; i++)
#pragma unroll
                for (int j = 0; j < 8; j++) acc[i][j] = fmaf(a[i], bv[j], acc[i][j]);
        }
        __syncthreads();
    }
    // epilogue: col = h*64 + d ; row = b*1024 + n ; dst[b,h,n,d]
    const int col0 = n0 + tx * 8;
    const int h = col0 >> 6;
    const int d0 = col0 & 63;            // multiple of 8, span of 8 stays in-head
#pragma unroll
    for (int i = 0; i < 8; i++) {
        int row = m0 + ty * 8 + i;
        int bb = row >> 10, nn = row & 1023;
        float* dst = outp + ((size_t)(bb * H_ + h) << 16) + nn * 64 + d0;
        *(float4*)dst       = make_float4(acc[i][0], acc[i][1], acc[i][2], acc[i][3]);
        *(float4*)(dst + 4) = make_float4(acc[i][4], acc[i][5], acc[i][6], acc[i][7]);
    }
}

// ---------------------------------------------------------------------------
// Kernel 2: per-(tensor,head) partial sums for BN stats. 1024 blocks.
// block bid: t = bid/512, h = (bid%512)/64, slice s = bid%64 (b = s/8, chunk = s%8)
// ---------------------------------------------------------------------------
__global__ void __launch_bounds__(256) bn_partial_kernel() {
    int bid = blockIdx.x;
    int t = bid >> 9;
    int rest = bid & 511;
    int h = rest >> 6;
    int s = rest & 63;
    int b = s >> 3, chunk = s & 7;
    const float* p = (t ? g_k : g_q) + (size_t)(b * H_ + h) * 65536 + chunk * 8192;
    const float4* p4 = (const float4*)p;
    int tid = threadIdx.x;
    float s1 = 0.f, s2 = 0.f;
#pragma unroll
    for (int j = 0; j < 8; j++) {
        float4 v = p4[tid + j * 256];
        s1 += v.x + v.y + v.z + v.w;
        s2 += v.x * v.x + v.y * v.y + v.z * v.z + v.w * v.w;
    }
#pragma unroll
    for (int o = 16; o; o >>= 1) {
        s1 += __shfl_xor_sync(0xffffffffu, s1, o);
        s2 += __shfl_xor_sync(0xffffffffu, s2, o);
    }
    __shared__ float red[16];
    if ((tid & 31) == 0) { red[(tid >> 5) * 2] = s1; red[(tid >> 5) * 2 + 1] = s2; }
    __syncthreads();
    if (tid == 0) {
        float a = 0.f, c = 0.f;
        for (int wq = 0; wq < 8; wq++) { a += red[wq * 2]; c += red[wq * 2 + 1]; }
        g_part[bid * 2] = a;
        g_part[bid * 2 + 1] = c;
    }
}

__global__ void bn_finalize_kernel() {
    int tid = threadIdx.x;
    if (tid < 16) {
        int t = tid >> 3, h = tid & 7;
        int base = t * 512 + h * 64;
        float s1 = 0.f, s2 = 0.f;
        for (int s = 0; s < 64; s++) {
            s1 += g_part[(base + s) * 2];
            s2 += g_part[(base + s) * 2 + 1];
        }
        float mean = s1 * (1.f / (float)HEAD_ELEMS_);
        float var = s2 * (1.f / (float)HEAD_ELEMS_) - mean * mean;
        g_stats[tid * 2] = mean;
        g_stats[tid * 2 + 1] = rsqrtf(var + 1e-5f);
    }
}

// ---------------------------------------------------------------------------
// Kernel 3: apply BN (affine) + L2 normalize each 64-row, in place.
// One warp per (tensor,b,h,n) row; 131072 rows total.
// ---------------------------------------------------------------------------
__global__ void __launch_bounds__(256) normalize_kernel(const float* __restrict__ bnw,
                                                        const float* __restrict__ bnb) {
    int gw = (blockIdx.x * blockDim.x + threadIdx.x) >> 5;
    int lane = threadIdx.x & 31;
    int t = gw >> 16;
    int rem = gw & 65535;            // (b*8+h)*1024 + n
    int h = (rem >> 10) & 7;
    float* p = (t ? g_k : g_q) + (size_t)rem * 64;
    float mean = g_stats[(t * 8 + h) * 2];
    float rstd = g_stats[(t * 8 + h) * 2 + 1];
    float w = bnw[h], bia = bnb[h];
    float2 v = *(float2*)(p + lane * 2);
    float x0 = (v.x - mean) * rstd * w + bia;
    float x1 = (v.y - mean) * rstd * w + bia;
    float ss = x0 * x0 + x1 * x1;
#pragma unroll
    for (int o = 16; o; o >>= 1) ss += __shfl_xor_sync(0xffffffffu, ss, o);
    float nrm = sqrtf(ss);
    float inv = 1.f / fmaxf(nrm, 1e-12f);
    v.x = x0 * inv; v.y = x1 * inv;
    *(float2*)(p + lane * 2) = v;
}

// ---------------------------------------------------------------------------
// Kernel 4: S^T[b,h,m,n] = (Kn[m] . Qn[n]) / 16. Batched 1024x1024x64 GEMM.
// 128x128 tile, 8x8 per thread, k=64 in 4 chunks of 16.
// ---------------------------------------------------------------------------
__global__ void __launch_bounds__(256) gemm_scores_kernel() {
    __shared__ float As[16][132];
    __shared__ float Bs[16][132];
    const int tid = threadIdx.x;
    const int bh = blockIdx.z;
    const float* A = g_k + (size_t)bh * 65536;   // rows m
    const float* Bq = g_q + (size_t)bh * 65536;  // rows n
    float* Cp = g_scores + (size_t)bh * 1048576;
    const int m0 = blockIdx.y * 128;
    const int n0 = blockIdx.x * 128;
    const int tx = tid & 15, ty = tid >> 4;

    float acc[8][8];
#pragma unroll
    for (int i = 0; i < 8; i++)
#pragma unroll
        for (int j = 0; j < 8; j++) acc[i][j] = 0.f;

    for (int kt = 0; kt < HD_; kt += 16) {
#pragma unroll
        for (int i = 0; i < 2; i++) {
            int idx = tid + i * 256;
            int r = idx >> 2;
            int kq = idx & 3;
            float4 va = *(const float4*)(A + (size_t)(m0 + r) * HD_ + kt + kq * 4);
            As[kq * 4 + 0][r] = va.x; As[kq * 4 + 1][r] = va.y;
            As[kq * 4 + 2][r] = va.z; As[kq * 4 + 3][r] = va.w;
            float4 vb = *(const float4*)(Bq + (size_t)(n0 + r) * HD_ + kt + kq * 4);
            Bs[kq * 4 + 0][r] = vb.x; Bs[kq * 4 + 1][r] = vb.y;
            Bs[kq * 4 + 2][r] = vb.z; Bs[kq * 4 + 3][r] = vb.w;
        }
        __syncthreads();
#pragma unroll
        for (int kk = 0; kk < 16; kk++) {
            float a[8], bv[8];
            *(float4*)(a)     = *(const float4*)&As[kk][ty * 8];
            *(float4*)(a + 4) = *(const float4*)&As[kk][ty * 8 + 4];
            *(float4*)(bv)     = *(const float4*)&Bs[kk][tx * 8];
            *(float4*)(bv + 4) = *(const float4*)&Bs[kk][tx * 8 + 4];
#pragma unroll
            for (int i = 0; i < 8; i++)
#pragma unroll
                for (int j = 0; j < 8; j++) acc[i][j] = fmaf(a[i], bv[j], acc[i][j]);
        }
        __syncthreads();
    }
#pragma unroll
    for (int i = 0; i < 8; i++) {
        float* dst = Cp + (size_t)(m0 + ty * 8 + i) * 1024 + n0 + tx * 8;
        *(float4*)dst = make_float4(acc[i][0] * SCALE_, acc[i][1] * SCALE_,
                                    acc[i][2] * SCALE_, acc[i][3] * SCALE_);
        *(float4*)(dst + 4) = make_float4(acc[i][4] * SCALE_, acc[i][5] * SCALE_,
                                          acc[i][6] * SCALE_, acc[i][7] * SCALE_);
    }
}

// ---------------------------------------------------------------------------
// Kernel 5: sparsemax along n per (b,h,m) via Michelot fixed point,
// one warp per row (32 regs), then 32m x 128n smem transpose for coalesced
// writes to out[b, n, h*1024 + m].
// ---------------------------------------------------------------------------
__global__ void __launch_bounds__(1024) sparsemax_kernel(float* __restrict__ out) {
    __shared__ float tile[128][33];
    const int bid = blockIdx.x;        // 2048 = 64 bh * 32 mblocks
    const int bh = bid >> 5;
    const int mblk = bid & 31;
    const int b = bh >> 3, h = bh & 7;
    const int w = threadIdx.x >> 5, lane = threadIdx.x & 31;
    const int m = mblk * 32 + w;
    const float* row = g_scores + (size_t)bh * 1048576 + (size_t)m * 1024;

    float z[32];
#pragma unroll
    for (int j = 0; j < 32; j++) z[j] = row[j * 32 + lane];

    float mx = z[0];
#pragma unroll
    for (int j = 1; j < 32; j++) mx = fmaxf(mx, z[j]);
#pragma unroll
    for (int o = 16; o; o >>= 1) mx = fmaxf(mx, __shfl_xor_sync(0xffffffffu, mx, o));
#pragma unroll
    for (int j = 0; j < 32; j++) z[j] -= mx;

    float s = 0.f;
#pragma unroll
    for (int j = 0; j < 32; j++) s += z[j];
#pragma unroll
    for (int o = 16; o; o >>= 1) s += __shfl_xor_sync(0xffffffffu, s, o);

    float tau = (s - 1.f) * (1.f / 1024.f);
    int cprev = 1024;
    for (int it = 0; it < 64; it++) {
        float ls = 0.f;
        int lc = 0;
#pragma unroll
        for (int j = 0; j < 32; j++) {
            if (z[j] > tau) { ls += z[j]; lc++; }
        }
#pragma unroll
        for (int o = 16; o; o >>= 1) {
            ls += __shfl_xor_sync(0xffffffffu, ls, o);
            lc += __shfl_xor_sync(0xffffffffu, lc, o);
        }
        tau = (ls - 1.f) / (float)lc;   // lc >= 1 always (max elem = 0 > tau)
        if (lc == cprev) break;         // active set stable -> exact fixed point
        cprev = lc;
    }

#pragma unroll
    for (int j = 0; j < 32; j++) z[j] = fmaxf(z[j] - tau, 0.f);

    const size_t outbase = (size_t)b * ((size_t)N_ * 8192) + (size_t)h * 1024 + mblk * 32;
#pragma unroll 1
    for (int g = 0; g < 8; g++) {
#pragma unroll
        for (int q = 0; q < 4; q++) tile[q * 32 + lane][w] = z[g * 4 + q];
        __syncthreads();
#pragma unroll
        for (int k = 0; k < 4; k++) {
            int flat = threadIdx.x + k * 1024;
            int nl = flat >> 5, ml = flat & 31;
            out[outbase + (size_t)(g * 128 + nl) * 8192 + ml] = tile[nl][ml];
        }
        __syncthreads();
    }
}

// ---------------------------------------------------------------------------
extern "C" void kernel_launch(void* const* d_in, const int* in_sizes, int n_in,
                              void* d_out, int out_size) {
    (void)in_sizes; (void)n_in; (void)out_size;
    const float* x   = (const float*)d_in[0];
    const float* qw  = (const float*)d_in[1];
    const float* kw  = (const float*)d_in[2];
    const float* bnw = (const float*)d_in[3];
    const float* bnb = (const float*)d_in[4];
    float* out = (float*)d_out;

    dim3 g1(4, 64, 2);                       // KS/128, ROWS/128, {q,k}
    gemm_qk_kernel<<<g1, 256>>>(x, qw, kw);
    bn_partial_kernel<<<1024, 256>>>();
    bn_finalize_kernel<<<1, 32>>>();
    normalize_kernel<<<16384, 256>>>(bnw, bnb);
    dim3 g2(8, 8, 64);                       // N/128, N/128, B*H
    gemm_scores_kernel<<<g2, 256>>>();
    sparsemax_kernel<<<2048, 1024>>>(out);
}